// round 9
// baseline (speedup 1.0000x reference)
#include <cuda_runtime.h>
#include <math.h>
#include <stdint.h>

#define NN 100000
#define EE 1600000
#define RR 8
#define GG 128
#define HH 64
#define CC 512   // RR*HH
#define SCAN_B 512
#define NBLK ((NN + SCAN_B - 1) / SCAN_B)   // 196

// ---------------- scratch ----------------
__device__ float g_xw[(size_t)RR * NN * HH];   // [r][n][h]
__device__ float g_WT[GG * CC];                // [k][r*64+o]
__device__ float g_sq[RR * NN];
__device__ float g_sk[RR * NN];
__device__ int   g_rs[EE];
__device__ int   g_dstl[EE];
__device__ int   g_sorted[EE];
__device__ int   g_cnt[NN];
__device__ int   g_wpos[NN];
__device__ int   g_off[NN];
__device__ int   g_scan[NN];
__device__ int   g_bsum[256];
__device__ int   g_bpre[256];
__device__ float g_x1[NN * HH];
__device__ float g_bnsum[HH];
__device__ float g_bnsqs[HH];
__device__ float g_bnscale[HH];
__device__ float g_bnshift[HH];

// ---------------- sort-by-dst pipeline ----------------
__global__ void k_zero() {
    int i = blockIdx.x * blockDim.x + threadIdx.x;
    if (i < NN) { g_cnt[i] = 0; g_wpos[i] = 0; }
    if (i < HH) { g_bnsum[i] = 0.f; g_bnsqs[i] = 0.f; }
}

__global__ void k_decode(const int* __restrict__ ei, const int* __restrict__ et) {
    int e = blockIdx.x * blockDim.x + threadIdx.x;
    if (e >= EE) return;
    int s = min(max(ei[e], 0), NN - 1);
    int d = min(max(ei[EE + e], 0), NN - 1);
    int r = min(max(et[e], 0), RR - 1);
    g_rs[e]   = r * NN + s;
    g_dstl[e] = d;
    atomicAdd(&g_cnt[d], 1);
}

__global__ void k_scan1() {
    __shared__ int s[SCAN_B];
    int tid = threadIdx.x;
    int i = blockIdx.x * SCAN_B + tid;
    int v = (i < NN) ? g_cnt[i] : 0;
    s[tid] = v;
    __syncthreads();
    for (int d = 1; d < SCAN_B; d <<= 1) {
        int t = (tid >= d) ? s[tid - d] : 0;
        __syncthreads();
        s[tid] += t;
        __syncthreads();
    }
    if (i < NN) g_scan[i] = s[tid];
    if (tid == SCAN_B - 1) g_bsum[blockIdx.x] = s[tid];
}

__global__ void k_scan2() {
    __shared__ int s[256];
    int tid = threadIdx.x;
    int v = (tid < NBLK) ? g_bsum[tid] : 0;
    s[tid] = v;
    __syncthreads();
    for (int d = 1; d < 256; d <<= 1) {
        int t = (tid >= d) ? s[tid - d] : 0;
        __syncthreads();
        s[tid] += t;
        __syncthreads();
    }
    if (tid < NBLK) g_bpre[tid] = s[tid] - v;
}

__global__ void k_scan3() {
    int i = blockIdx.x * blockDim.x + threadIdx.x;
    if (i >= NN) return;
    g_off[i] = g_scan[i] - g_cnt[i] + g_bpre[i >> 9];
}

__global__ void k_scatter() {
    int e = blockIdx.x * blockDim.x + threadIdx.x;
    if (e >= EE) return;
    int d = g_dstl[e];
    int pos = g_off[d] + atomicAdd(&g_wpos[d], 1);
    g_sorted[pos] = g_rs[e];
}

// W [R,K,H] -> WT [K, r*64+o]
__global__ void k_wt(const float* __restrict__ W, int K) {
    int idx = blockIdx.x * blockDim.x + threadIdx.x;
    if (idx >= K * CC) return;
    int i = idx / CC, c = idx % CC;
    int r = c >> 6, o = c & 63;
    g_WT[idx] = W[((size_t)r * K + i) * HH + o];
}

// ---------------- tf32 tensor-core GEMM + fused scores ----------------
__device__ __forceinline__ uint32_t f2tf32(float f) {
    uint32_t u;
    asm("cvt.rna.tf32.f32 %0, %1;" : "=r"(u) : "f"(f));
    return u;
}

#define APAD 36
#define BPAD 136   // stride mod 32 banks = 8 -> conflict-free B fragment loads

__global__ void __launch_bounds__(256)
k_gemm(const float* __restrict__ Aparam, int M, int K, int useX1,
       const float* __restrict__ qv_g, const float* __restrict__ kv_g) {
    const float* __restrict__ A = useX1 ? g_x1 : Aparam;
    __shared__ float As[128 * APAD];
    __shared__ float Bs[32 * BPAD];
    __shared__ float qs[64], ks[64];

    int rp = blockIdx.x;
    int rowBase = blockIdx.y * 128;
    int tid = threadIdx.x;
    int warp = tid >> 5, lane = tid & 31;
    int wr = warp >> 1, wc = warp & 1;
    int g = lane >> 2, t = lane & 3;

    if (tid < 64)        qs[tid] = qv_g[tid];
    else if (tid < 128)  ks[tid - 64] = kv_g[tid - 64];

    float acc[2][8][4];
    #pragma unroll
    for (int i = 0; i < 2; i++)
        #pragma unroll
        for (int j = 0; j < 8; j++)
            #pragma unroll
            for (int l = 0; l < 4; l++) acc[i][j][l] = 0.f;

    const uint32_t* Asu = (const uint32_t*)As;
    const uint32_t* Bsu = (const uint32_t*)Bs;
    int nChunks = K >> 5;

    for (int c = 0; c < nChunks; c++) {
        int kbase = c << 5;
        __syncthreads();
        #pragma unroll
        for (int it = 0; it < 4; it++) {
            int idx = it * 256 + tid;
            int row = idx >> 3;
            int kq = idx & 7;
            int grow = rowBase + row;
            float4 v = make_float4(0.f, 0.f, 0.f, 0.f);
            if (grow < M) v = *(const float4*)(A + (size_t)grow * K + kbase + kq * 4);
            uint4 u = make_uint4(f2tf32(v.x), f2tf32(v.y), f2tf32(v.z), f2tf32(v.w));
            *(uint4*)(As + row * APAD + kq * 4) = *(uint4*)&u;
        }
        #pragma unroll
        for (int it = 0; it < 4; it++) {
            int idx = it * 256 + tid;
            int kk = idx >> 5;
            int nq = idx & 31;
            float4 v = *(const float4*)(g_WT + (size_t)(kbase + kk) * CC + rp * 128 + nq * 4);
            uint4 u = make_uint4(f2tf32(v.x), f2tf32(v.y), f2tf32(v.z), f2tf32(v.w));
            *(uint4*)(Bs + kk * BPAD + nq * 4) = *(uint4*)&u;
        }
        __syncthreads();

        #pragma unroll
        for (int k8 = 0; k8 < 4; k8++) {
            int kk = k8 * 8;
            uint32_t af[2][4];
            #pragma unroll
            for (int mt = 0; mt < 2; mt++) {
                int r0 = wr * 32 + mt * 16;
                af[mt][0] = Asu[(r0 + g) * APAD + kk + t];
                af[mt][1] = Asu[(r0 + g + 8) * APAD + kk + t];
                af[mt][2] = Asu[(r0 + g) * APAD + kk + t + 4];
                af[mt][3] = Asu[(r0 + g + 8) * APAD + kk + t + 4];
            }
            #pragma unroll
            for (int nt = 0; nt < 8; nt++) {
                int n0 = wc * 64 + nt * 8 + g;
                uint32_t b0 = Bsu[(kk + t) * BPAD + n0];
                uint32_t b1 = Bsu[(kk + t + 4) * BPAD + n0];
                #pragma unroll
                for (int mt = 0; mt < 2; mt++) {
                    asm volatile(
                        "mma.sync.aligned.m16n8k8.row.col.f32.tf32.tf32.f32 "
                        "{%0,%1,%2,%3}, {%4,%5,%6,%7}, {%8,%9}, {%0,%1,%2,%3};\n"
                        : "+f"(acc[mt][nt][0]), "+f"(acc[mt][nt][1]),
                          "+f"(acc[mt][nt][2]), "+f"(acc[mt][nt][3])
                        : "r"(af[mt][0]), "r"(af[mt][1]), "r"(af[mt][2]), "r"(af[mt][3]),
                          "r"(b0), "r"(b1));
                }
            }
        }
    }

    int rel = 2 * rp + wc;
    float qv[16], kv[16];
    #pragma unroll
    for (int nt = 0; nt < 8; nt++) {
        int o0 = nt * 8 + 2 * t;
        qv[2 * nt] = qs[o0]; qv[2 * nt + 1] = qs[o0 + 1];
        kv[2 * nt] = ks[o0]; kv[2 * nt + 1] = ks[o0 + 1];
    }
    #pragma unroll
    for (int mt = 0; mt < 2; mt++) {
        #pragma unroll
        for (int h = 0; h < 2; h++) {
            int row_l = wr * 32 + mt * 16 + g + h * 8;
            int grow = rowBase + row_l;
            bool ok = (grow < M);
            float pq = 0.f, pk = 0.f;
            #pragma unroll
            for (int nt = 0; nt < 8; nt++) {
                float c0 = acc[mt][nt][h * 2 + 0];
                float c1 = acc[mt][nt][h * 2 + 1];
                int o0 = nt * 8 + 2 * t;
                if (ok) {
                    float2 v = make_float2(c0, c1);
                    *(float2*)(g_xw + ((size_t)rel * NN + grow) * 64 + o0) = v;
                }
                pq += c0 * qv[2 * nt] + c1 * qv[2 * nt + 1];
                pk += c0 * kv[2 * nt] + c1 * kv[2 * nt + 1];
            }
            pq += __shfl_xor_sync(0xffffffffu, pq, 1);
            pq += __shfl_xor_sync(0xffffffffu, pq, 2);
            pk += __shfl_xor_sync(0xffffffffu, pk, 1);
            pk += __shfl_xor_sync(0xffffffffu, pk, 2);
            if (ok && t == 0) {
                g_sq[rel * NN + grow] = pq;
                g_sk[rel * NN + grow] = pk;
            }
        }
    }
}

// ---------------- segmented softmax-aggregate: one warp per node ----------------
__global__ void k_agg(const float* __restrict__ b, float* outParam, int mode) {
    int gw = (blockIdx.x * blockDim.x + threadIdx.x) >> 5;
    int lane = threadIdx.x & 31;
    if (gw >= NN) return;
    float* dst = (mode == 1) ? g_x1 : outParam;
    int node = gw;
    int beg = g_off[node];
    int cnt = g_cnt[node];

    float2 acc = make_float2(0.f, 0.f);
    float2 acc2 = make_float2(0.f, 0.f);
    float denom = 0.f;

    if (cnt <= 32) {
        int rs_l = 0;
        float a_l = -INFINITY;
        if (lane < cnt) {
            rs_l = g_sorted[beg + lane];
            int r = rs_l / NN;
            float a = g_sq[r * NN + node] + g_sk[rs_l];
            a_l = a > 0.f ? a : 0.2f * a;
        }
        float m = a_l;
        #pragma unroll
        for (int off = 16; off; off >>= 1)
            m = fmaxf(m, __shfl_xor_sync(0xffffffffu, m, off));
        float w_l = (lane < cnt) ? __expf(a_l - m) : 0.f;
        float ds = w_l;
        #pragma unroll
        for (int off = 16; off; off >>= 1)
            ds += __shfl_xor_sync(0xffffffffu, ds, off);
        denom = ds;
        int i = 0;
        for (; i + 4 <= cnt; i += 4) {
            int rs0 = __shfl_sync(0xffffffffu, rs_l, i);
            int rs1 = __shfl_sync(0xffffffffu, rs_l, i + 1);
            int rs2 = __shfl_sync(0xffffffffu, rs_l, i + 2);
            int rs3 = __shfl_sync(0xffffffffu, rs_l, i + 3);
            float w0 = __shfl_sync(0xffffffffu, w_l, i);
            float w1 = __shfl_sync(0xffffffffu, w_l, i + 1);
            float w2 = __shfl_sync(0xffffffffu, w_l, i + 2);
            float w3 = __shfl_sync(0xffffffffu, w_l, i + 3);
            float2 v0 = ((const float2*)g_xw)[(size_t)rs0 * 32 + lane];
            float2 v1 = ((const float2*)g_xw)[(size_t)rs1 * 32 + lane];
            float2 v2 = ((const float2*)g_xw)[(size_t)rs2 * 32 + lane];
            float2 v3 = ((const float2*)g_xw)[(size_t)rs3 * 32 + lane];
            acc.x  += w0 * v0.x + w1 * v1.x;
            acc.y  += w0 * v0.y + w1 * v1.y;
            acc2.x += w2 * v2.x + w3 * v3.x;
            acc2.y += w2 * v2.y + w3 * v3.y;
        }
        for (; i < cnt; i++) {
            int rs0 = __shfl_sync(0xffffffffu, rs_l, i);
            float w0 = __shfl_sync(0xffffffffu, w_l, i);
            float2 v0 = ((const float2*)g_xw)[(size_t)rs0 * 32 + lane];
            acc.x += w0 * v0.x;
            acc.y += w0 * v0.y;
        }
    } else {
        float m = -INFINITY;
        for (int i = lane; i < cnt; i += 32) {
            int rs = g_sorted[beg + i];
            int r = rs / NN;
            float a = g_sq[r * NN + node] + g_sk[rs];
            a = a > 0.f ? a : 0.2f * a;
            m = fmaxf(m, a);
        }
        #pragma unroll
        for (int off = 16; off; off >>= 1)
            m = fmaxf(m, __shfl_xor_sync(0xffffffffu, m, off));
        for (int i = 0; i < cnt; i++) {
            int rs = g_sorted[beg + i];
            int r = rs / NN;
            float a = g_sq[r * NN + node] + g_sk[rs];
            a = a > 0.f ? a : 0.2f * a;
            float w = __expf(a - m);
            denom += w;
            float2 v = ((const float2*)g_xw)[(size_t)rs * 32 + lane];
            acc.x += w * v.x;
            acc.y += w * v.y;
        }
    }

    acc.x += acc2.x; acc.y += acc2.y;
    float inv = 1.f / (denom + 1e-16f);
    float2 bb = ((const float2*)b)[lane];
    float ox = acc.x * inv + bb.x;
    float oy = acc.y * inv + bb.y;
    if (mode == 1) { ox = fmaxf(ox, 0.f); oy = fmaxf(oy, 0.f); }
    ((float2*)dst)[(size_t)node * 32 + lane] = make_float2(ox, oy);
}

// ---------------- batchnorm ----------------
__global__ void k_bnstats(const float* __restrict__ out) {
    int gw = (blockIdx.x * blockDim.x + threadIdx.x) >> 5;
    int lane = threadIdx.x & 31;
    const int CHUNK = 98;
    int n0 = gw * CHUNK;
    float2 s = make_float2(0.f, 0.f), s2 = make_float2(0.f, 0.f);
    for (int n = n0; n < n0 + CHUNK && n < NN; n++) {
        float2 v = ((const float2*)out)[(size_t)n * 32 + lane];
        s.x += v.x; s.y += v.y;
        s2.x += v.x * v.x; s2.y += v.y * v.y;
    }
    atomicAdd(&g_bnsum[2 * lane], s.x);     atomicAdd(&g_bnsum[2 * lane + 1], s.y);
    atomicAdd(&g_bnsqs[2 * lane], s2.x);    atomicAdd(&g_bnsqs[2 * lane + 1], s2.y);
}

__global__ void k_bnfinal(const float* __restrict__ gamma, const float* __restrict__ beta) {
    int h = threadIdx.x;
    if (h < HH) {
        float mean = g_bnsum[h] * (1.f / NN);
        float var  = g_bnsqs[h] * (1.f / NN) - mean * mean;
        float sc = gamma[h] * rsqrtf(var + 1e-5f);
        g_bnscale[h] = sc;
        g_bnshift[h] = beta[h] - mean * sc;
    }
}

__global__ void k_bnapply(float* __restrict__ out) {
    int t = blockIdx.x * blockDim.x + threadIdx.x;
    if (t >= NN * 16) return;
    int h4 = t & 15;
    float4 v  = ((float4*)out)[t];
    float4 sc = ((const float4*)g_bnscale)[h4];
    float4 sh = ((const float4*)g_bnshift)[h4];
    v.x = v.x * sc.x + sh.x; v.x = v.x > 0.f ? v.x : 0.01f * v.x;
    v.y = v.y * sc.y + sh.y; v.y = v.y > 0.f ? v.y : 0.01f * v.y;
    v.z = v.z * sc.z + sh.z; v.z = v.z > 0.f ? v.z : 0.01f * v.z;
    v.w = v.w * sc.w + sh.w; v.w = v.w > 0.f ? v.w : 0.01f * v.w;
    ((float4*)out)[t] = v;
}

// ---------------- launch ----------------
extern "C" void kernel_launch(void* const* d_in, const int* in_sizes, int n_in,
                              void* d_out, int out_size) {
    const float* x     = (const float*)d_in[0];
    const int*   ei    = (const int*)d_in[1];
    const int*   et    = (const int*)d_in[2];
    const float* W1    = (const float*)d_in[3];
    const float* q1    = (const float*)d_in[4];
    const float* k1    = (const float*)d_in[5];
    const float* b1    = (const float*)d_in[6];
    const float* W2    = (const float*)d_in[7];
    const float* q2    = (const float*)d_in[8];
    const float* k2    = (const float*)d_in[9];
    const float* b2    = (const float*)d_in[10];
    const float* gamma = (const float*)d_in[11];
    const float* beta  = (const float*)d_in[12];
    float* out = (float*)d_out;

    const int TPB = 256;
    dim3 gemmGrid(4, (NN + 127) / 128);

    k_zero<<<(NN + TPB - 1) / TPB, TPB>>>();                       // 0
    k_decode<<<(EE + TPB - 1) / TPB, TPB>>>(ei, et);               // 1
    k_wt<<<(GG * CC + TPB - 1) / TPB, TPB>>>(W1, GG);              // 2
    k_gemm<<<gemmGrid, TPB>>>(x, NN, GG, 0, q1, k1);               // 3 <- profiled
    k_scan1<<<NBLK, SCAN_B>>>();                                   // 4
    k_scan2<<<1, 256>>>();                                         // 5
    k_scan3<<<(NN + TPB - 1) / TPB, TPB>>>();                      // 6
    k_scatter<<<(EE + TPB - 1) / TPB, TPB>>>();                    // 7
    k_agg<<<(NN * 32 + TPB - 1) / TPB, TPB>>>(b1, nullptr, 1);     // 8

    // ---- layer 2 ----
    k_wt<<<(HH * CC + TPB - 1) / TPB, TPB>>>(W2, HH);
    k_gemm<<<gemmGrid, TPB>>>(nullptr, NN, HH, 1, q2, k2);
    k_agg<<<(NN * 32 + TPB - 1) / TPB, TPB>>>(b2, out, 0);

    // ---- batchnorm + leaky ----
    k_bnstats<<<(1024 * 32) / TPB, TPB>>>(out);
    k_bnfinal<<<1, HH>>>(gamma, beta);
    k_bnapply<<<(NN * 16 + TPB - 1) / TPB, TPB>>>(out);
}

// round 10
// speedup vs baseline: 1.0349x; 1.0349x over previous
#include <cuda_runtime.h>
#include <math.h>
#include <stdint.h>

#define NN 100000
#define EE 1600000
#define RR 8
#define GG 128
#define HH 64
#define CC 512   // RR*HH
#define SCAN_B 512
#define NBLK ((NN + SCAN_B - 1) / SCAN_B)   // 196

// ---------------- scratch ----------------
__device__ float g_xw[(size_t)RR * NN * HH];   // [r][n][h]
__device__ float g_xa[(size_t)NN * GG];        // tf32-rounded input features
__device__ float g_WT[GG * CC];                // [k][r*64+o], tf32-rounded
__device__ float g_sq[RR * NN];
__device__ float g_sk[RR * NN];
__device__ int   g_rs[EE];
__device__ int   g_dstl[EE];
__device__ int   g_sorted[EE];
__device__ int   g_cnt[NN];
__device__ int   g_wpos[NN];
__device__ int   g_off[NN];
__device__ int   g_scan[NN];
__device__ int   g_bsum[256];
__device__ int   g_bpre[256];
__device__ float g_x1[NN * HH];                // tf32-rounded layer-1 output
__device__ float g_bnsum[HH];
__device__ float g_bnsqs[HH];
__device__ float g_bnscale[HH];
__device__ float g_bnshift[HH];

__device__ __forceinline__ float ftf32(float f) {
    uint32_t u;
    asm("cvt.rna.tf32.f32 %0, %1;" : "=r"(u) : "f"(f));
    return __uint_as_float(u);
}

// ---------------- sort-by-dst pipeline ----------------
__global__ void k_zero() {
    int i = blockIdx.x * blockDim.x + threadIdx.x;
    if (i < NN) { g_cnt[i] = 0; g_wpos[i] = 0; }
    if (i < HH) { g_bnsum[i] = 0.f; g_bnsqs[i] = 0.f; }
}

__global__ void k_decode(const int* __restrict__ ei, const int* __restrict__ et) {
    int e = blockIdx.x * blockDim.x + threadIdx.x;
    if (e >= EE) return;
    int s = min(max(ei[e], 0), NN - 1);
    int d = min(max(ei[EE + e], 0), NN - 1);
    int r = min(max(et[e], 0), RR - 1);
    g_rs[e]   = r * NN + s;
    g_dstl[e] = d;
    atomicAdd(&g_cnt[d], 1);
}

__global__ void k_scan1() {
    __shared__ int s[SCAN_B];
    int tid = threadIdx.x;
    int i = blockIdx.x * SCAN_B + tid;
    int v = (i < NN) ? g_cnt[i] : 0;
    s[tid] = v;
    __syncthreads();
    for (int d = 1; d < SCAN_B; d <<= 1) {
        int t = (tid >= d) ? s[tid - d] : 0;
        __syncthreads();
        s[tid] += t;
        __syncthreads();
    }
    if (i < NN) g_scan[i] = s[tid];
    if (tid == SCAN_B - 1) g_bsum[blockIdx.x] = s[tid];
}

__global__ void k_scan2() {
    __shared__ int s[256];
    int tid = threadIdx.x;
    int v = (tid < NBLK) ? g_bsum[tid] : 0;
    s[tid] = v;
    __syncthreads();
    for (int d = 1; d < 256; d <<= 1) {
        int t = (tid >= d) ? s[tid - d] : 0;
        __syncthreads();
        s[tid] += t;
        __syncthreads();
    }
    if (tid < NBLK) g_bpre[tid] = s[tid] - v;
}

__global__ void k_scan3() {
    int i = blockIdx.x * blockDim.x + threadIdx.x;
    if (i >= NN) return;
    g_off[i] = g_scan[i] - g_cnt[i] + g_bpre[i >> 9];
}

__global__ void k_scatter() {
    int e = blockIdx.x * blockDim.x + threadIdx.x;
    if (e >= EE) return;
    int d = g_dstl[e];
    int pos = g_off[d] + atomicAdd(&g_wpos[d], 1);
    g_sorted[pos] = g_rs[e];
}

// W [R,K,H] -> WT [K, r*64+o], tf32-rounded at source
__global__ void k_wt(const float* __restrict__ W, int K) {
    int idx = blockIdx.x * blockDim.x + threadIdx.x;
    if (idx >= K * CC) return;
    int i = idx / CC, c = idx % CC;
    int r = c >> 6, o = c & 63;
    g_WT[idx] = ftf32(W[((size_t)r * K + i) * HH + o]);
}

// x -> g_xa, tf32-rounded
__global__ void k_cvtA(const float* __restrict__ x) {
    int i = blockIdx.x * blockDim.x + threadIdx.x;
    if (i >= NN * (GG / 4)) return;
    float4 v = ((const float4*)x)[i];
    v.x = ftf32(v.x); v.y = ftf32(v.y); v.z = ftf32(v.z); v.w = ftf32(v.w);
    ((float4*)g_xa)[i] = v;
}

// ---------------- tf32 tensor-core GEMM + fused scores ----------------
#define APAD 36
#define BPAD 136

__device__ __forceinline__ void cpa16(uint32_t smem_addr, const void* gptr, int sz) {
    asm volatile("cp.async.ca.shared.global [%0], [%1], 16, %2;\n"
                 :: "r"(smem_addr), "l"(gptr), "r"(sz));
}

__global__ void __launch_bounds__(256)
k_gemm(int M, int K, int useX1,
       const float* __restrict__ qv_g, const float* __restrict__ kv_g) {
    const float* __restrict__ A = useX1 ? g_x1 : g_xa;
    __shared__ float As[128 * APAD];
    __shared__ float Bs[32 * BPAD];
    __shared__ float qs[64], ks[64];

    int rp = blockIdx.x;
    int rowBase = blockIdx.y * 128;
    int tid = threadIdx.x;
    int warp = tid >> 5, lane = tid & 31;
    int wr = warp >> 1, wc = warp & 1;
    int g = lane >> 2, t = lane & 3;

    uint32_t AsS = (uint32_t)__cvta_generic_to_shared(As);
    uint32_t BsS = (uint32_t)__cvta_generic_to_shared(Bs);

    if (tid < 64)        qs[tid] = qv_g[tid];
    else if (tid < 128)  ks[tid - 64] = kv_g[tid - 64];

    float acc[2][8][4];
    #pragma unroll
    for (int i = 0; i < 2; i++)
        #pragma unroll
        for (int j = 0; j < 8; j++)
            #pragma unroll
            for (int l = 0; l < 4; l++) acc[i][j][l] = 0.f;

    const uint32_t* Asu = (const uint32_t*)As;
    const uint32_t* Bsu = (const uint32_t*)Bs;
    int nChunks = K >> 5;

    // per-thread cp.async coordinates
    int arow = tid >> 3, akq = (tid & 7) * 4;       // + it*32 rows
    int bkk = tid >> 5,  bnq = (tid & 31) * 4;      // + it*8 k-rows

    for (int c = 0; c < nChunks; c++) {
        int kbase = c << 5;
        __syncthreads();
        #pragma unroll
        for (int it = 0; it < 4; it++) {
            int row = arow + it * 32;
            int grow = rowBase + row;
            cpa16(AsS + (row * APAD + akq) * 4,
                  A + (size_t)grow * K + kbase + akq,
                  (grow < M) ? 16 : 0);
        }
        #pragma unroll
        for (int it = 0; it < 4; it++) {
            int kk = bkk + it * 8;
            cpa16(BsS + (kk * BPAD + bnq) * 4,
                  g_WT + (size_t)(kbase + kk) * CC + rp * 128 + bnq, 16);
        }
        asm volatile("cp.async.commit_group;\n");
        asm volatile("cp.async.wait_group 0;\n");
        __syncthreads();

        #pragma unroll
        for (int k8 = 0; k8 < 4; k8++) {
            int kk = k8 * 8;
            uint32_t af[2][4];
            #pragma unroll
            for (int mt = 0; mt < 2; mt++) {
                int r0 = wr * 32 + mt * 16;
                af[mt][0] = Asu[(r0 + g) * APAD + kk + t];
                af[mt][1] = Asu[(r0 + g + 8) * APAD + kk + t];
                af[mt][2] = Asu[(r0 + g) * APAD + kk + t + 4];
                af[mt][3] = Asu[(r0 + g + 8) * APAD + kk + t + 4];
            }
            #pragma unroll
            for (int nt = 0; nt < 8; nt++) {
                int n0 = wc * 64 + nt * 8 + g;
                uint32_t b0 = Bsu[(kk + t) * BPAD + n0];
                uint32_t b1 = Bsu[(kk + t + 4) * BPAD + n0];
                #pragma unroll
                for (int mt = 0; mt < 2; mt++) {
                    asm volatile(
                        "mma.sync.aligned.m16n8k8.row.col.f32.tf32.tf32.f32 "
                        "{%0,%1,%2,%3}, {%4,%5,%6,%7}, {%8,%9}, {%0,%1,%2,%3};\n"
                        : "+f"(acc[mt][nt][0]), "+f"(acc[mt][nt][1]),
                          "+f"(acc[mt][nt][2]), "+f"(acc[mt][nt][3])
                        : "r"(af[mt][0]), "r"(af[mt][1]), "r"(af[mt][2]), "r"(af[mt][3]),
                          "r"(b0), "r"(b1));
                }
            }
        }
    }

    int rel = 2 * rp + wc;
    float qv[16], kv[16];
    #pragma unroll
    for (int nt = 0; nt < 8; nt++) {
        int o0 = nt * 8 + 2 * t;
        qv[2 * nt] = qs[o0]; qv[2 * nt + 1] = qs[o0 + 1];
        kv[2 * nt] = ks[o0]; kv[2 * nt + 1] = ks[o0 + 1];
    }
    #pragma unroll
    for (int mt = 0; mt < 2; mt++) {
        #pragma unroll
        for (int h = 0; h < 2; h++) {
            int row_l = wr * 32 + mt * 16 + g + h * 8;
            int grow = rowBase + row_l;
            bool ok = (grow < M);
            float pq = 0.f, pk = 0.f;
            #pragma unroll
            for (int nt = 0; nt < 8; nt++) {
                float c0 = acc[mt][nt][h * 2 + 0];
                float c1 = acc[mt][nt][h * 2 + 1];
                int o0 = nt * 8 + 2 * t;
                if (ok) {
                    float2 v = make_float2(c0, c1);
                    *(float2*)(g_xw + ((size_t)rel * NN + grow) * 64 + o0) = v;
                }
                pq += c0 * qv[2 * nt] + c1 * qv[2 * nt + 1];
                pk += c0 * kv[2 * nt] + c1 * kv[2 * nt + 1];
            }
            pq += __shfl_xor_sync(0xffffffffu, pq, 1);
            pq += __shfl_xor_sync(0xffffffffu, pq, 2);
            pk += __shfl_xor_sync(0xffffffffu, pk, 1);
            pk += __shfl_xor_sync(0xffffffffu, pk, 2);
            if (ok && t == 0) {
                g_sq[rel * NN + grow] = pq;
                g_sk[rel * NN + grow] = pk;
            }
        }
    }
}

// ---------------- segmented softmax-aggregate: one warp per node ----------------
__global__ void k_agg(const float* __restrict__ b, float* outParam, int mode) {
    int gw = (blockIdx.x * blockDim.x + threadIdx.x) >> 5;
    int lane = threadIdx.x & 31;
    if (gw >= NN) return;
    float* dst = (mode == 1) ? g_x1 : outParam;
    int node = gw;
    int beg = g_off[node];
    int cnt = g_cnt[node];

    float2 acc = make_float2(0.f, 0.f);
    float denom = 0.f;

    if (cnt <= 32) {
        int rs_l = 0;
        float a_l = -INFINITY;
        if (lane < cnt) {
            rs_l = g_sorted[beg + lane];
            int r = rs_l / NN;
            float a = g_sq[r * NN + node] + g_sk[rs_l];
            a_l = a > 0.f ? a : 0.2f * a;
        }
        float m = a_l;
        #pragma unroll
        for (int off = 16; off; off >>= 1)
            m = fmaxf(m, __shfl_xor_sync(0xffffffffu, m, off));
        float w_l = (lane < cnt) ? __expf(a_l - m) : 0.f;
        float ds = w_l;
        #pragma unroll
        for (int off = 16; off; off >>= 1)
            ds += __shfl_xor_sync(0xffffffffu, ds, off);
        denom = ds;
        int i = 0;
        for (; i + 2 <= cnt; i += 2) {
            int rs0 = __shfl_sync(0xffffffffu, rs_l, i);
            int rs1 = __shfl_sync(0xffffffffu, rs_l, i + 1);
            float w0 = __shfl_sync(0xffffffffu, w_l, i);
            float w1 = __shfl_sync(0xffffffffu, w_l, i + 1);
            float2 v0 = ((const float2*)g_xw)[(size_t)rs0 * 32 + lane];
            float2 v1 = ((const float2*)g_xw)[(size_t)rs1 * 32 + lane];
            acc.x += w0 * v0.x + w1 * v1.x;
            acc.y += w0 * v0.y + w1 * v1.y;
        }
        if (i < cnt) {
            int rs0 = __shfl_sync(0xffffffffu, rs_l, i);
            float w0 = __shfl_sync(0xffffffffu, w_l, i);
            float2 v0 = ((const float2*)g_xw)[(size_t)rs0 * 32 + lane];
            acc.x += w0 * v0.x;
            acc.y += w0 * v0.y;
        }
    } else {
        float m = -INFINITY;
        for (int i = lane; i < cnt; i += 32) {
            int rs = g_sorted[beg + i];
            int r = rs / NN;
            float a = g_sq[r * NN + node] + g_sk[rs];
            a = a > 0.f ? a : 0.2f * a;
            m = fmaxf(m, a);
        }
        #pragma unroll
        for (int off = 16; off; off >>= 1)
            m = fmaxf(m, __shfl_xor_sync(0xffffffffu, m, off));
        for (int i = 0; i < cnt; i++) {
            int rs = g_sorted[beg + i];
            int r = rs / NN;
            float a = g_sq[r * NN + node] + g_sk[rs];
            a = a > 0.f ? a : 0.2f * a;
            float w = __expf(a - m);
            denom += w;
            float2 v = ((const float2*)g_xw)[(size_t)rs * 32 + lane];
            acc.x += w * v.x;
            acc.y += w * v.y;
        }
    }

    float inv = 1.f / (denom + 1e-16f);
    float2 bb = ((const float2*)b)[lane];
    float ox = acc.x * inv + bb.x;
    float oy = acc.y * inv + bb.y;
    if (mode == 1) {
        ox = ftf32(fmaxf(ox, 0.f));   // round at source: layer-2 GEMM skips cvt
        oy = ftf32(fmaxf(oy, 0.f));
    }
    ((float2*)dst)[(size_t)node * 32 + lane] = make_float2(ox, oy);
}

// ---------------- batchnorm ----------------
__global__ void k_bnstats(const float* __restrict__ out) {
    int gw = (blockIdx.x * blockDim.x + threadIdx.x) >> 5;
    int lane = threadIdx.x & 31;
    const int CHUNK = 98;
    int n0 = gw * CHUNK;
    float2 s = make_float2(0.f, 0.f), s2 = make_float2(0.f, 0.f);
    for (int n = n0; n < n0 + CHUNK && n < NN; n++) {
        float2 v = ((const float2*)out)[(size_t)n * 32 + lane];
        s.x += v.x; s.y += v.y;
        s2.x += v.x * v.x; s2.y += v.y * v.y;
    }
    atomicAdd(&g_bnsum[2 * lane], s.x);     atomicAdd(&g_bnsum[2 * lane + 1], s.y);
    atomicAdd(&g_bnsqs[2 * lane], s2.x);    atomicAdd(&g_bnsqs[2 * lane + 1], s2.y);
}

__global__ void k_bnfinal(const float* __restrict__ gamma, const float* __restrict__ beta) {
    int h = threadIdx.x;
    if (h < HH) {
        float mean = g_bnsum[h] * (1.f / NN);
        float var  = g_bnsqs[h] * (1.f / NN) - mean * mean;
        float sc = gamma[h] * rsqrtf(var + 1e-5f);
        g_bnscale[h] = sc;
        g_bnshift[h] = beta[h] - mean * sc;
    }
}

__global__ void k_bnapply(float* __restrict__ out) {
    int t = blockIdx.x * blockDim.x + threadIdx.x;
    if (t >= NN * 16) return;
    int h4 = t & 15;
    float4 v  = ((float4*)out)[t];
    float4 sc = ((const float4*)g_bnscale)[h4];
    float4 sh = ((const float4*)g_bnshift)[h4];
    v.x = v.x * sc.x + sh.x; v.x = v.x > 0.f ? v.x : 0.01f * v.x;
    v.y = v.y * sc.y + sh.y; v.y = v.y > 0.f ? v.y : 0.01f * v.y;
    v.z = v.z * sc.z + sh.z; v.z = v.z > 0.f ? v.z : 0.01f * v.z;
    v.w = v.w * sc.w + sh.w; v.w = v.w > 0.f ? v.w : 0.01f * v.w;
    ((float4*)out)[t] = v;
}

// ---------------- launch ----------------
extern "C" void kernel_launch(void* const* d_in, const int* in_sizes, int n_in,
                              void* d_out, int out_size) {
    const float* x     = (const float*)d_in[0];
    const int*   ei    = (const int*)d_in[1];
    const int*   et    = (const int*)d_in[2];
    const float* W1    = (const float*)d_in[3];
    const float* q1    = (const float*)d_in[4];
    const float* k1    = (const float*)d_in[5];
    const float* b1    = (const float*)d_in[6];
    const float* W2    = (const float*)d_in[7];
    const float* q2    = (const float*)d_in[8];
    const float* k2    = (const float*)d_in[9];
    const float* b2    = (const float*)d_in[10];
    const float* gamma = (const float*)d_in[11];
    const float* beta  = (const float*)d_in[12];
    float* out = (float*)d_out;

    const int TPB = 256;
    dim3 gemmGrid(4, (NN + 127) / 128);

    k_zero<<<(NN + TPB - 1) / TPB, TPB>>>();                       // 0
    k_cvtA<<<(NN * 32 + TPB - 1) / TPB, TPB>>>(x);                 // 1
    k_wt<<<(GG * CC + TPB - 1) / TPB, TPB>>>(W1, GG);              // 2
    k_gemm<<<gemmGrid, TPB>>>(NN, GG, 0, q1, k1);                  // 3 <- profiled
    k_decode<<<(EE + TPB - 1) / TPB, TPB>>>(ei, et);               // 4
    k_scan1<<<NBLK, SCAN_B>>>();                                   // 5
    k_scan2<<<1, 256>>>();                                         // 6
    k_scan3<<<(NN + TPB - 1) / TPB, TPB>>>();                      // 7
    k_scatter<<<(EE + TPB - 1) / TPB, TPB>>>();                    // 8
    k_agg<<<(NN * 32 + TPB - 1) / TPB, TPB>>>(b1, nullptr, 1);     // 9

    // ---- layer 2 ----
    k_wt<<<(HH * CC + TPB - 1) / TPB, TPB>>>(W2, HH);
    k_gemm<<<gemmGrid, TPB>>>(NN, HH, 1, q2, k2);
    k_agg<<<(NN * 32 + TPB - 1) / TPB, TPB>>>(b2, out, 0);

    // ---- batchnorm + leaky ----
    k_bnstats<<<(1024 * 32) / TPB, TPB>>>(out);
    k_bnfinal<<<1, HH>>>(gamma, beta);
    k_bnapply<<<(NN * 16 + TPB - 1) / TPB, TPB>>>(out);
}

// round 11
// speedup vs baseline: 1.1204x; 1.0826x over previous
#include <cuda_runtime.h>
#include <cuda_fp16.h>
#include <math.h>
#include <stdint.h>

#define NN 100000
#define EE 1600000
#define RR 8
#define GG 128
#define HH 64
#define CC 512   // RR*HH
#define SCAN_B 512
#define NBLK ((NN + SCAN_B - 1) / SCAN_B)   // 196

// ---------------- scratch ----------------
__device__ __half g_xw[(size_t)RR * NN * HH];  // [r][n][h] fp16 (102 MB)
__device__ float g_xa[(size_t)NN * GG];        // tf32-rounded input features
__device__ float g_WT[GG * CC];                // [k][r*64+o], tf32-rounded
__device__ float g_sq[RR * NN];
__device__ float g_sk[RR * NN];
__device__ int   g_rs[EE];
__device__ int   g_dstl[EE];
__device__ int   g_sorted[EE];
__device__ int   g_cnt[NN];
__device__ int   g_wpos[NN];
__device__ int   g_off[NN];
__device__ int   g_scan[NN];
__device__ int   g_bsum[256];
__device__ int   g_bpre[256];
__device__ float g_x1[NN * HH];                // tf32-rounded layer-1 output
__device__ float g_bnsum[HH];
__device__ float g_bnsqs[HH];
__device__ float g_bnscale[HH];
__device__ float g_bnshift[HH];

__device__ __forceinline__ float ftf32(float f) {
    uint32_t u;
    asm("cvt.rna.tf32.f32 %0, %1;" : "=r"(u) : "f"(f));
    return __uint_as_float(u);
}

// ---------------- sort-by-dst pipeline ----------------
__global__ void k_zero() {
    int i = blockIdx.x * blockDim.x + threadIdx.x;
    if (i < NN) { g_cnt[i] = 0; g_wpos[i] = 0; }
    if (i < HH) { g_bnsum[i] = 0.f; g_bnsqs[i] = 0.f; }
}

__global__ void k_decode(const int* __restrict__ ei, const int* __restrict__ et) {
    int e = blockIdx.x * blockDim.x + threadIdx.x;
    if (e >= EE) return;
    int s = min(max(ei[e], 0), NN - 1);
    int d = min(max(ei[EE + e], 0), NN - 1);
    int r = min(max(et[e], 0), RR - 1);
    g_rs[e]   = r * NN + s;
    g_dstl[e] = d;
    atomicAdd(&g_cnt[d], 1);
}

__global__ void k_scan1() {
    __shared__ int s[SCAN_B];
    int tid = threadIdx.x;
    int i = blockIdx.x * SCAN_B + tid;
    int v = (i < NN) ? g_cnt[i] : 0;
    s[tid] = v;
    __syncthreads();
    for (int d = 1; d < SCAN_B; d <<= 1) {
        int t = (tid >= d) ? s[tid - d] : 0;
        __syncthreads();
        s[tid] += t;
        __syncthreads();
    }
    if (i < NN) g_scan[i] = s[tid];
    if (tid == SCAN_B - 1) g_bsum[blockIdx.x] = s[tid];
}

__global__ void k_scan2() {
    __shared__ int s[256];
    int tid = threadIdx.x;
    int v = (tid < NBLK) ? g_bsum[tid] : 0;
    s[tid] = v;
    __syncthreads();
    for (int d = 1; d < 256; d <<= 1) {
        int t = (tid >= d) ? s[tid - d] : 0;
        __syncthreads();
        s[tid] += t;
        __syncthreads();
    }
    if (tid < NBLK) g_bpre[tid] = s[tid] - v;
}

__global__ void k_scan3() {
    int i = blockIdx.x * blockDim.x + threadIdx.x;
    if (i >= NN) return;
    g_off[i] = g_scan[i] - g_cnt[i] + g_bpre[i >> 9];
}

__global__ void k_scatter() {
    int e = blockIdx.x * blockDim.x + threadIdx.x;
    if (e >= EE) return;
    int d = g_dstl[e];
    int pos = g_off[d] + atomicAdd(&g_wpos[d], 1);
    g_sorted[pos] = g_rs[e];
}

// W [R,K,H] -> WT [K, r*64+o], tf32-rounded at source
__global__ void k_wt(const float* __restrict__ W, int K) {
    int idx = blockIdx.x * blockDim.x + threadIdx.x;
    if (idx >= K * CC) return;
    int i = idx / CC, c = idx % CC;
    int r = c >> 6, o = c & 63;
    g_WT[idx] = ftf32(W[((size_t)r * K + i) * HH + o]);
}

// x -> g_xa, tf32-rounded
__global__ void k_cvtA(const float* __restrict__ x) {
    int i = blockIdx.x * blockDim.x + threadIdx.x;
    if (i >= NN * (GG / 4)) return;
    float4 v = ((const float4*)x)[i];
    v.x = ftf32(v.x); v.y = ftf32(v.y); v.z = ftf32(v.z); v.w = ftf32(v.w);
    ((float4*)g_xa)[i] = v;
}

// ---------------- tf32 tensor-core GEMM + fused scores ----------------
#define APAD 36
#define BPAD 136

__device__ __forceinline__ void cpa16(uint32_t smem_addr, const void* gptr, int sz) {
    asm volatile("cp.async.ca.shared.global [%0], [%1], 16, %2;\n"
                 :: "r"(smem_addr), "l"(gptr), "r"(sz));
}

__global__ void __launch_bounds__(256)
k_gemm(int M, int K, int useX1,
       const float* __restrict__ qv_g, const float* __restrict__ kv_g) {
    const float* __restrict__ A = useX1 ? g_x1 : g_xa;
    __shared__ float As[128 * APAD];
    __shared__ float Bs[32 * BPAD];
    __shared__ float qs[64], ks[64];

    int rp = blockIdx.x;
    int rowBase = blockIdx.y * 128;
    int tid = threadIdx.x;
    int warp = tid >> 5, lane = tid & 31;
    int wr = warp >> 1, wc = warp & 1;
    int g = lane >> 2, t = lane & 3;

    uint32_t AsS = (uint32_t)__cvta_generic_to_shared(As);
    uint32_t BsS = (uint32_t)__cvta_generic_to_shared(Bs);

    if (tid < 64)        qs[tid] = qv_g[tid];
    else if (tid < 128)  ks[tid - 64] = kv_g[tid - 64];

    float acc[2][8][4];
    #pragma unroll
    for (int i = 0; i < 2; i++)
        #pragma unroll
        for (int j = 0; j < 8; j++)
            #pragma unroll
            for (int l = 0; l < 4; l++) acc[i][j][l] = 0.f;

    const uint32_t* Asu = (const uint32_t*)As;
    const uint32_t* Bsu = (const uint32_t*)Bs;
    int nChunks = K >> 5;

    int arow = tid >> 3, akq = (tid & 7) * 4;
    int bkk = tid >> 5,  bnq = (tid & 31) * 4;

    for (int c = 0; c < nChunks; c++) {
        int kbase = c << 5;
        __syncthreads();
        #pragma unroll
        for (int it = 0; it < 4; it++) {
            int row = arow + it * 32;
            int grow = rowBase + row;
            cpa16(AsS + (row * APAD + akq) * 4,
                  A + (size_t)grow * K + kbase + akq,
                  (grow < M) ? 16 : 0);
        }
        #pragma unroll
        for (int it = 0; it < 4; it++) {
            int kk = bkk + it * 8;
            cpa16(BsS + (kk * BPAD + bnq) * 4,
                  g_WT + (size_t)(kbase + kk) * CC + rp * 128 + bnq, 16);
        }
        asm volatile("cp.async.commit_group;\n");
        asm volatile("cp.async.wait_group 0;\n");
        __syncthreads();

        #pragma unroll
        for (int k8 = 0; k8 < 4; k8++) {
            int kk = k8 * 8;
            uint32_t af[2][4];
            #pragma unroll
            for (int mt = 0; mt < 2; mt++) {
                int r0 = wr * 32 + mt * 16;
                af[mt][0] = Asu[(r0 + g) * APAD + kk + t];
                af[mt][1] = Asu[(r0 + g + 8) * APAD + kk + t];
                af[mt][2] = Asu[(r0 + g) * APAD + kk + t + 4];
                af[mt][3] = Asu[(r0 + g + 8) * APAD + kk + t + 4];
            }
            #pragma unroll
            for (int nt = 0; nt < 8; nt++) {
                int n0 = wc * 64 + nt * 8 + g;
                uint32_t b0 = Bsu[(kk + t) * BPAD + n0];
                uint32_t b1 = Bsu[(kk + t + 4) * BPAD + n0];
                #pragma unroll
                for (int mt = 0; mt < 2; mt++) {
                    asm volatile(
                        "mma.sync.aligned.m16n8k8.row.col.f32.tf32.tf32.f32 "
                        "{%0,%1,%2,%3}, {%4,%5,%6,%7}, {%8,%9}, {%0,%1,%2,%3};\n"
                        : "+f"(acc[mt][nt][0]), "+f"(acc[mt][nt][1]),
                          "+f"(acc[mt][nt][2]), "+f"(acc[mt][nt][3])
                        : "r"(af[mt][0]), "r"(af[mt][1]), "r"(af[mt][2]), "r"(af[mt][3]),
                          "r"(b0), "r"(b1));
                }
            }
        }
    }

    int rel = 2 * rp + wc;
    float qv[16], kv[16];
    #pragma unroll
    for (int nt = 0; nt < 8; nt++) {
        int o0 = nt * 8 + 2 * t;
        qv[2 * nt] = qs[o0]; qv[2 * nt + 1] = qs[o0 + 1];
        kv[2 * nt] = ks[o0]; kv[2 * nt + 1] = ks[o0 + 1];
    }
    __half2* xwh = (__half2*)g_xw;
    #pragma unroll
    for (int mt = 0; mt < 2; mt++) {
        #pragma unroll
        for (int h = 0; h < 2; h++) {
            int row_l = wr * 32 + mt * 16 + g + h * 8;
            int grow = rowBase + row_l;
            bool ok = (grow < M);
            float pq = 0.f, pk = 0.f;
            #pragma unroll
            for (int nt = 0; nt < 8; nt++) {
                float c0 = acc[mt][nt][h * 2 + 0];
                float c1 = acc[mt][nt][h * 2 + 1];
                if (ok) {
                    xwh[((size_t)rel * NN + grow) * 32 + nt * 4 + t] =
                        __floats2half2_rn(c0, c1);
                }
                pq += c0 * qv[2 * nt] + c1 * qv[2 * nt + 1];
                pk += c0 * kv[2 * nt] + c1 * kv[2 * nt + 1];
            }
            pq += __shfl_xor_sync(0xffffffffu, pq, 1);
            pq += __shfl_xor_sync(0xffffffffu, pq, 2);
            pk += __shfl_xor_sync(0xffffffffu, pk, 1);
            pk += __shfl_xor_sync(0xffffffffu, pk, 2);
            if (ok && t == 0) {
                g_sq[rel * NN + grow] = pq;
                g_sk[rel * NN + grow] = pk;
            }
        }
    }
}

// ---------------- segmented softmax-aggregate: one warp per node ----------------
// g_xw fp16: one edge row = 64 halfs = 128 B = one line; lane reads half2.
__global__ void k_agg(const float* __restrict__ b, float* outParam, int mode) {
    int gw = (blockIdx.x * blockDim.x + threadIdx.x) >> 5;
    int lane = threadIdx.x & 31;
    if (gw >= NN) return;
    float* dst = (mode == 1) ? g_x1 : outParam;
    int node = gw;
    int beg = g_off[node];
    int cnt = g_cnt[node];
    const __half2* xwh = (const __half2*)g_xw;

    float2 acc = make_float2(0.f, 0.f);
    float denom = 0.f;

    if (cnt <= 32) {
        int rs_l = 0;
        float a_l = -INFINITY;
        if (lane < cnt) {
            rs_l = g_sorted[beg + lane];
            int r = rs_l / NN;
            float a = g_sq[r * NN + node] + g_sk[rs_l];
            a_l = a > 0.f ? a : 0.2f * a;
        }
        float m = a_l;
        #pragma unroll
        for (int off = 16; off; off >>= 1)
            m = fmaxf(m, __shfl_xor_sync(0xffffffffu, m, off));
        float w_l = (lane < cnt) ? __expf(a_l - m) : 0.f;
        float ds = w_l;
        #pragma unroll
        for (int off = 16; off; off >>= 1)
            ds += __shfl_xor_sync(0xffffffffu, ds, off);
        denom = ds;
        int i = 0;
        for (; i + 2 <= cnt; i += 2) {
            int rs0 = __shfl_sync(0xffffffffu, rs_l, i);
            int rs1 = __shfl_sync(0xffffffffu, rs_l, i + 1);
            float w0 = __shfl_sync(0xffffffffu, w_l, i);
            float w1 = __shfl_sync(0xffffffffu, w_l, i + 1);
            float2 v0 = __half22float2(xwh[(size_t)rs0 * 32 + lane]);
            float2 v1 = __half22float2(xwh[(size_t)rs1 * 32 + lane]);
            acc.x += w0 * v0.x + w1 * v1.x;
            acc.y += w0 * v0.y + w1 * v1.y;
        }
        if (i < cnt) {
            int rs0 = __shfl_sync(0xffffffffu, rs_l, i);
            float w0 = __shfl_sync(0xffffffffu, w_l, i);
            float2 v0 = __half22float2(xwh[(size_t)rs0 * 32 + lane]);
            acc.x += w0 * v0.x;
            acc.y += w0 * v0.y;
        }
    } else {
        float m = -INFINITY;
        for (int i = lane; i < cnt; i += 32) {
            int rs = g_sorted[beg + i];
            int r = rs / NN;
            float a = g_sq[r * NN + node] + g_sk[rs];
            a = a > 0.f ? a : 0.2f * a;
            m = fmaxf(m, a);
        }
        #pragma unroll
        for (int off = 16; off; off >>= 1)
            m = fmaxf(m, __shfl_xor_sync(0xffffffffu, m, off));
        for (int i = 0; i < cnt; i++) {
            int rs = g_sorted[beg + i];
            int r = rs / NN;
            float a = g_sq[r * NN + node] + g_sk[rs];
            a = a > 0.f ? a : 0.2f * a;
            float w = __expf(a - m);
            denom += w;
            float2 v = __half22float2(xwh[(size_t)rs * 32 + lane]);
            acc.x += w * v.x;
            acc.y += w * v.y;
        }
    }

    float inv = 1.f / (denom + 1e-16f);
    float2 bb = ((const float2*)b)[lane];
    float ox = acc.x * inv + bb.x;
    float oy = acc.y * inv + bb.y;
    if (mode == 1) {
        ox = ftf32(fmaxf(ox, 0.f));
        oy = ftf32(fmaxf(oy, 0.f));
    }
    ((float2*)dst)[(size_t)node * 32 + lane] = make_float2(ox, oy);
}

// ---------------- batchnorm ----------------
__global__ void k_bnstats(const float* __restrict__ out) {
    int gw = (blockIdx.x * blockDim.x + threadIdx.x) >> 5;
    int lane = threadIdx.x & 31;
    const int CHUNK = 98;
    int n0 = gw * CHUNK;
    float2 s = make_float2(0.f, 0.f), s2 = make_float2(0.f, 0.f);
    for (int n = n0; n < n0 + CHUNK && n < NN; n++) {
        float2 v = ((const float2*)out)[(size_t)n * 32 + lane];
        s.x += v.x; s.y += v.y;
        s2.x += v.x * v.x; s2.y += v.y * v.y;
    }
    atomicAdd(&g_bnsum[2 * lane], s.x);     atomicAdd(&g_bnsum[2 * lane + 1], s.y);
    atomicAdd(&g_bnsqs[2 * lane], s2.x);    atomicAdd(&g_bnsqs[2 * lane + 1], s2.y);
}

__global__ void k_bnfinal(const float* __restrict__ gamma, const float* __restrict__ beta) {
    int h = threadIdx.x;
    if (h < HH) {
        float mean = g_bnsum[h] * (1.f / NN);
        float var  = g_bnsqs[h] * (1.f / NN) - mean * mean;
        float sc = gamma[h] * rsqrtf(var + 1e-5f);
        g_bnscale[h] = sc;
        g_bnshift[h] = beta[h] - mean * sc;
    }
}

__global__ void k_bnapply(float* __restrict__ out) {
    int t = blockIdx.x * blockDim.x + threadIdx.x;
    if (t >= NN * 16) return;
    int h4 = t & 15;
    float4 v  = ((float4*)out)[t];
    float4 sc = ((const float4*)g_bnscale)[h4];
    float4 sh = ((const float4*)g_bnshift)[h4];
    v.x = v.x * sc.x + sh.x; v.x = v.x > 0.f ? v.x : 0.01f * v.x;
    v.y = v.y * sc.y + sh.y; v.y = v.y > 0.f ? v.y : 0.01f * v.y;
    v.z = v.z * sc.z + sh.z; v.z = v.z > 0.f ? v.z : 0.01f * v.z;
    v.w = v.w * sc.w + sh.w; v.w = v.w > 0.f ? v.w : 0.01f * v.w;
    ((float4*)out)[t] = v;
}

// ---------------- launch ----------------
extern "C" void kernel_launch(void* const* d_in, const int* in_sizes, int n_in,
                              void* d_out, int out_size) {
    const float* x     = (const float*)d_in[0];
    const int*   ei    = (const int*)d_in[1];
    const int*   et    = (const int*)d_in[2];
    const float* W1    = (const float*)d_in[3];
    const float* q1    = (const float*)d_in[4];
    const float* k1    = (const float*)d_in[5];
    const float* b1    = (const float*)d_in[6];
    const float* W2    = (const float*)d_in[7];
    const float* q2    = (const float*)d_in[8];
    const float* k2    = (const float*)d_in[9];
    const float* b2    = (const float*)d_in[10];
    const float* gamma = (const float*)d_in[11];
    const float* beta  = (const float*)d_in[12];
    float* out = (float*)d_out;

    const int TPB = 256;
    dim3 gemmGrid(4, (NN + 127) / 128);

    k_zero<<<(NN + TPB - 1) / TPB, TPB>>>();                       // 0
    k_cvtA<<<(NN * 32 + TPB - 1) / TPB, TPB>>>(x);                 // 1
    k_wt<<<(GG * CC + TPB - 1) / TPB, TPB>>>(W1, GG);              // 2
    k_gemm<<<gemmGrid, TPB>>>(NN, GG, 0, q1, k1);                  // 3 <- profiled
    k_decode<<<(EE + TPB - 1) / TPB, TPB>>>(ei, et);               // 4
    k_scan1<<<NBLK, SCAN_B>>>();                                   // 5
    k_scan2<<<1, 256>>>();                                         // 6
    k_scan3<<<(NN + TPB - 1) / TPB, TPB>>>();                      // 7
    k_scatter<<<(EE + TPB - 1) / TPB, TPB>>>();                    // 8
    k_agg<<<(NN * 32 + TPB - 1) / TPB, TPB>>>(b1, nullptr, 1);     // 9

    // ---- layer 2 ----
    k_wt<<<(HH * CC + TPB - 1) / TPB, TPB>>>(W2, HH);
    k_gemm<<<gemmGrid, TPB>>>(NN, HH, 1, q2, k2);
    k_agg<<<(NN * 32 + TPB - 1) / TPB, TPB>>>(b2, out, 0);

    // ---- batchnorm + leaky ----
    k_bnstats<<<(1024 * 32) / TPB, TPB>>>(out);
    k_bnfinal<<<1, HH>>>(gamma, beta);
    k_bnapply<<<(NN * 16 + TPB - 1) / TPB, TPB>>>(out);
}

// round 12
// speedup vs baseline: 1.1935x; 1.0653x over previous
#include <cuda_runtime.h>
#include <cuda_fp16.h>
#include <math.h>
#include <stdint.h>

#define NN 100000
#define EE 1600000
#define RR 8
#define GG 128
#define HH 64
#define CC 512   // RR*HH
#define SCAN_B 512
#define NBLK ((NN + SCAN_B - 1) / SCAN_B)   // 196

// ---------------- scratch ----------------
__device__ __half g_xw[(size_t)RR * NN * HH];  // [r][n][h] fp16
__device__ __half g_xa[(size_t)NN * GG];       // fp16 input features
__device__ __half g_WT[GG * CC];               // [r*64+o][k] fp16 (n-major!)
__device__ float g_sq[RR * NN];
__device__ float g_sk[RR * NN];
__device__ int   g_rs[EE];
__device__ int   g_dstl[EE];
__device__ int   g_sorted[EE];
__device__ int   g_cnt[NN];
__device__ int   g_wpos[NN];
__device__ int   g_off[NN];
__device__ int   g_scan[NN];
__device__ int   g_bsum[256];
__device__ int   g_bpre[256];
__device__ __half g_x1[NN * HH];               // fp16 layer-1 output
__device__ float g_bnsum[HH];
__device__ float g_bnsqs[HH];
__device__ float g_bnscale[HH];
__device__ float g_bnshift[HH];

// ---------------- sort-by-dst pipeline ----------------
__global__ void k_zero() {
    int i = blockIdx.x * blockDim.x + threadIdx.x;
    if (i < NN) { g_cnt[i] = 0; g_wpos[i] = 0; }
    if (i < HH) { g_bnsum[i] = 0.f; g_bnsqs[i] = 0.f; }
}

__global__ void k_decode(const int* __restrict__ ei, const int* __restrict__ et) {
    int e = blockIdx.x * blockDim.x + threadIdx.x;
    if (e >= EE) return;
    int s = min(max(ei[e], 0), NN - 1);
    int d = min(max(ei[EE + e], 0), NN - 1);
    int r = min(max(et[e], 0), RR - 1);
    g_rs[e]   = r * NN + s;
    g_dstl[e] = d;
    atomicAdd(&g_cnt[d], 1);
}

__global__ void k_scan1() {
    __shared__ int s[SCAN_B];
    int tid = threadIdx.x;
    int i = blockIdx.x * SCAN_B + tid;
    int v = (i < NN) ? g_cnt[i] : 0;
    s[tid] = v;
    __syncthreads();
    for (int d = 1; d < SCAN_B; d <<= 1) {
        int t = (tid >= d) ? s[tid - d] : 0;
        __syncthreads();
        s[tid] += t;
        __syncthreads();
    }
    if (i < NN) g_scan[i] = s[tid];
    if (tid == SCAN_B - 1) g_bsum[blockIdx.x] = s[tid];
}

__global__ void k_scan2() {
    __shared__ int s[256];
    int tid = threadIdx.x;
    int v = (tid < NBLK) ? g_bsum[tid] : 0;
    s[tid] = v;
    __syncthreads();
    for (int d = 1; d < 256; d <<= 1) {
        int t = (tid >= d) ? s[tid - d] : 0;
        __syncthreads();
        s[tid] += t;
        __syncthreads();
    }
    if (tid < NBLK) g_bpre[tid] = s[tid] - v;
}

__global__ void k_scan3() {
    int i = blockIdx.x * blockDim.x + threadIdx.x;
    if (i >= NN) return;
    g_off[i] = g_scan[i] - g_cnt[i] + g_bpre[i >> 9];
}

__global__ void k_scatter() {
    int e = blockIdx.x * blockDim.x + threadIdx.x;
    if (e >= EE) return;
    int d = g_dstl[e];
    int pos = g_off[d] + atomicAdd(&g_wpos[d], 1);
    g_sorted[pos] = g_rs[e];
}

// W [R,K,H] -> WT [r*64+o][k] fp16 (n-major rows, k contiguous)
__global__ void k_wt(const float* __restrict__ W, int K) {
    int idx = blockIdx.x * blockDim.x + threadIdx.x;
    if (idx >= K * CC) return;
    int c = idx / K, i = idx % K;       // c = r*64+o
    int r = c >> 6, o = c & 63;
    g_WT[idx] = __float2half_rn(W[((size_t)r * K + i) * HH + o]);
}

// x -> g_xa fp16
__global__ void k_cvtA(const float* __restrict__ x) {
    int i = blockIdx.x * blockDim.x + threadIdx.x;
    if (i >= NN * (GG / 4)) return;
    float4 v = ((const float4*)x)[i];
    __half2 h0 = __floats2half2_rn(v.x, v.y);
    __half2 h1 = __floats2half2_rn(v.z, v.w);
    ((uint2*)g_xa)[i] = make_uint2(*(uint32_t*)&h0, *(uint32_t*)&h1);
}

// ---------------- fp16 tensor-core GEMM + fused scores ----------------
#define PADH 40   // halfs per smem row (80 B): conflict-free ldmatrix + half2 LDS

__device__ __forceinline__ void cpa16(uint32_t smem_addr, const void* gptr, int sz) {
    asm volatile("cp.async.ca.shared.global [%0], [%1], 16, %2;\n"
                 :: "r"(smem_addr), "l"(gptr), "r"(sz));
}

// block tile 128 rows x 128 cols (2 relations), 8 warps of 32x64,
// mma.m16n8k16 fp16 inputs / fp32 accum, k-chunks of 32 via smem.
__global__ void __launch_bounds__(256)
k_gemm(int M, int K, int useX1,
       const float* __restrict__ qv_g, const float* __restrict__ kv_g) {
    const __half* __restrict__ A = useX1 ? g_x1 : g_xa;
    __shared__ __half Ah[128 * PADH];   // [row][k] per chunk
    __shared__ __half Bh[128 * PADH];   // [n][k] per chunk
    __shared__ float qs[64], ks[64];

    int rp = blockIdx.x;
    int rowBase = blockIdx.y * 128;
    int tid = threadIdx.x;
    int warp = tid >> 5, lane = tid & 31;
    int wr = warp >> 1, wc = warp & 1;
    int g = lane >> 2, t = lane & 3;

    uint32_t AhS = (uint32_t)__cvta_generic_to_shared(Ah);
    uint32_t BhS = (uint32_t)__cvta_generic_to_shared(Bh);

    if (tid < 64)        qs[tid] = qv_g[tid];
    else if (tid < 128)  ks[tid - 64] = kv_g[tid - 64];

    float acc[2][8][4];
    #pragma unroll
    for (int i = 0; i < 2; i++)
        #pragma unroll
        for (int j = 0; j < 8; j++)
            #pragma unroll
            for (int l = 0; l < 4; l++) acc[i][j][l] = 0.f;

    const uint32_t* Bsu = (const uint32_t*)Bh;
    int nChunks = K >> 5;

    // cp.async coords: 128 rows x 4 chunks(16B) each for A and B
    int lrow = tid >> 1;                    // 0..127
    int lc8  = (tid & 1) * 8;               // halfs 0 / 8 ; second pass +16
    // ldmatrix lane address components
    int lm_row = (lane & 7) + ((lane >> 3) & 1) * 8;
    int lm_c8  = (lane >> 4) * 8;

    for (int c = 0; c < nChunks; c++) {
        int kbase = c << 5;
        __syncthreads();
        #pragma unroll
        for (int p = 0; p < 2; p++) {
            int c8 = lc8 + p * 16;          // halfs offset within chunk
            int grow = rowBase + lrow;
            cpa16(AhS + (lrow * PADH + c8) * 2,
                  A + (size_t)grow * K + kbase + c8,
                  (grow < M) ? 16 : 0);
            cpa16(BhS + (lrow * PADH + c8) * 2,
                  g_WT + (size_t)(rp * 128 + lrow) * K + kbase + c8, 16);
        }
        asm volatile("cp.async.commit_group;\n");
        asm volatile("cp.async.wait_group 0;\n");
        __syncthreads();

        #pragma unroll
        for (int ks16 = 0; ks16 < 2; ks16++) {
            uint32_t af[2][4];
            #pragma unroll
            for (int mt = 0; mt < 2; mt++) {
                int row = wr * 32 + mt * 16 + lm_row;
                uint32_t addr = AhS + (row * PADH + ks16 * 16 + lm_c8) * 2;
                asm volatile(
                    "ldmatrix.sync.aligned.m8n8.x4.shared.b16 {%0,%1,%2,%3}, [%4];\n"
                    : "=r"(af[mt][0]), "=r"(af[mt][1]), "=r"(af[mt][2]), "=r"(af[mt][3])
                    : "r"(addr));
            }
            #pragma unroll
            for (int nt = 0; nt < 8; nt++) {
                int n = wc * 64 + nt * 8 + g;
                uint32_t b0 = Bsu[n * (PADH / 2) + ks16 * 8 + t];
                uint32_t b1 = Bsu[n * (PADH / 2) + ks16 * 8 + t + 4];
                #pragma unroll
                for (int mt = 0; mt < 2; mt++) {
                    asm volatile(
                        "mma.sync.aligned.m16n8k16.row.col.f32.f16.f16.f32 "
                        "{%0,%1,%2,%3}, {%4,%5,%6,%7}, {%8,%9}, {%0,%1,%2,%3};\n"
                        : "+f"(acc[mt][nt][0]), "+f"(acc[mt][nt][1]),
                          "+f"(acc[mt][nt][2]), "+f"(acc[mt][nt][3])
                        : "r"(af[mt][0]), "r"(af[mt][1]), "r"(af[mt][2]), "r"(af[mt][3]),
                          "r"(b0), "r"(b1));
                }
            }
        }
    }

    int rel = 2 * rp + wc;
    float qv[16], kv[16];
    #pragma unroll
    for (int nt = 0; nt < 8; nt++) {
        int o0 = nt * 8 + 2 * t;
        qv[2 * nt] = qs[o0]; qv[2 * nt + 1] = qs[o0 + 1];
        kv[2 * nt] = ks[o0]; kv[2 * nt + 1] = ks[o0 + 1];
    }
    __half2* xwh = (__half2*)g_xw;
    #pragma unroll
    for (int mt = 0; mt < 2; mt++) {
        #pragma unroll
        for (int h = 0; h < 2; h++) {
            int row_l = wr * 32 + mt * 16 + g + h * 8;
            int grow = rowBase + row_l;
            bool ok = (grow < M);
            float pq = 0.f, pk = 0.f;
            #pragma unroll
            for (int nt = 0; nt < 8; nt++) {
                float c0 = acc[mt][nt][h * 2 + 0];
                float c1 = acc[mt][nt][h * 2 + 1];
                if (ok) {
                    xwh[((size_t)rel * NN + grow) * 32 + nt * 4 + t] =
                        __floats2half2_rn(c0, c1);
                }
                pq += c0 * qv[2 * nt] + c1 * qv[2 * nt + 1];
                pk += c0 * kv[2 * nt] + c1 * kv[2 * nt + 1];
            }
            pq += __shfl_xor_sync(0xffffffffu, pq, 1);
            pq += __shfl_xor_sync(0xffffffffu, pq, 2);
            pk += __shfl_xor_sync(0xffffffffu, pk, 1);
            pk += __shfl_xor_sync(0xffffffffu, pk, 2);
            if (ok && t == 0) {
                g_sq[rel * NN + grow] = pq;
                g_sk[rel * NN + grow] = pk;
            }
        }
    }
}

// ---------------- segmented softmax-aggregate: one warp per node ----------------
__global__ void k_agg(const float* __restrict__ b, float* outParam, int mode) {
    int gw = (blockIdx.x * blockDim.x + threadIdx.x) >> 5;
    int lane = threadIdx.x & 31;
    if (gw >= NN) return;
    int node = gw;
    int beg = g_off[node];
    int cnt = g_cnt[node];
    const __half2* xwh = (const __half2*)g_xw;

    float2 acc = make_float2(0.f, 0.f);
    float denom = 0.f;

    if (cnt <= 32) {
        int rs_l = 0;
        float a_l = -INFINITY;
        if (lane < cnt) {
            rs_l = g_sorted[beg + lane];
            int r = rs_l / NN;
            float a = g_sq[r * NN + node] + g_sk[rs_l];
            a_l = a > 0.f ? a : 0.2f * a;
        }
        float m = a_l;
        #pragma unroll
        for (int off = 16; off; off >>= 1)
            m = fmaxf(m, __shfl_xor_sync(0xffffffffu, m, off));
        float w_l = (lane < cnt) ? __expf(a_l - m) : 0.f;
        float ds = w_l;
        #pragma unroll
        for (int off = 16; off; off >>= 1)
            ds += __shfl_xor_sync(0xffffffffu, ds, off);
        denom = ds;
        int i = 0;
        for (; i + 2 <= cnt; i += 2) {
            int rs0 = __shfl_sync(0xffffffffu, rs_l, i);
            int rs1 = __shfl_sync(0xffffffffu, rs_l, i + 1);
            float w0 = __shfl_sync(0xffffffffu, w_l, i);
            float w1 = __shfl_sync(0xffffffffu, w_l, i + 1);
            float2 v0 = __half22float2(xwh[(size_t)rs0 * 32 + lane]);
            float2 v1 = __half22float2(xwh[(size_t)rs1 * 32 + lane]);
            acc.x += w0 * v0.x + w1 * v1.x;
            acc.y += w0 * v0.y + w1 * v1.y;
        }
        if (i < cnt) {
            int rs0 = __shfl_sync(0xffffffffu, rs_l, i);
            float w0 = __shfl_sync(0xffffffffu, w_l, i);
            float2 v0 = __half22float2(xwh[(size_t)rs0 * 32 + lane]);
            acc.x += w0 * v0.x;
            acc.y += w0 * v0.y;
        }
    } else {
        float m = -INFINITY;
        for (int i = lane; i < cnt; i += 32) {
            int rs = g_sorted[beg + i];
            int r = rs / NN;
            float a = g_sq[r * NN + node] + g_sk[rs];
            a = a > 0.f ? a : 0.2f * a;
            m = fmaxf(m, a);
        }
        #pragma unroll
        for (int off = 16; off; off >>= 1)
            m = fmaxf(m, __shfl_xor_sync(0xffffffffu, m, off));
        for (int i = 0; i < cnt; i++) {
            int rs = g_sorted[beg + i];
            int r = rs / NN;
            float a = g_sq[r * NN + node] + g_sk[rs];
            a = a > 0.f ? a : 0.2f * a;
            float w = __expf(a - m);
            denom += w;
            float2 v = __half22float2(xwh[(size_t)rs * 32 + lane]);
            acc.x += w * v.x;
            acc.y += w * v.y;
        }
    }

    float inv = 1.f / (denom + 1e-16f);
    float2 bb = ((const float2*)b)[lane];
    float ox = acc.x * inv + bb.x;
    float oy = acc.y * inv + bb.y;
    if (mode == 1) {
        ox = fmaxf(ox, 0.f);
        oy = fmaxf(oy, 0.f);
        ((__half2*)g_x1)[(size_t)node * 32 + lane] = __floats2half2_rn(ox, oy);
    } else {
        ((float2*)outParam)[(size_t)node * 32 + lane] = make_float2(ox, oy);
    }
}

// ---------------- batchnorm ----------------
__global__ void k_bnstats(const float* __restrict__ out) {
    int gw = (blockIdx.x * blockDim.x + threadIdx.x) >> 5;
    int lane = threadIdx.x & 31;
    const int CHUNK = 98;
    int n0 = gw * CHUNK;
    float2 s = make_float2(0.f, 0.f), s2 = make_float2(0.f, 0.f);
    for (int n = n0; n < n0 + CHUNK && n < NN; n++) {
        float2 v = ((const float2*)out)[(size_t)n * 32 + lane];
        s.x += v.x; s.y += v.y;
        s2.x += v.x * v.x; s2.y += v.y * v.y;
    }
    atomicAdd(&g_bnsum[2 * lane], s.x);     atomicAdd(&g_bnsum[2 * lane + 1], s.y);
    atomicAdd(&g_bnsqs[2 * lane], s2.x);    atomicAdd(&g_bnsqs[2 * lane + 1], s2.y);
}

__global__ void k_bnfinal(const float* __restrict__ gamma, const float* __restrict__ beta) {
    int h = threadIdx.x;
    if (h < HH) {
        float mean = g_bnsum[h] * (1.f / NN);
        float var  = g_bnsqs[h] * (1.f / NN) - mean * mean;
        float sc = gamma[h] * rsqrtf(var + 1e-5f);
        g_bnscale[h] = sc;
        g_bnshift[h] = beta[h] - mean * sc;
    }
}

__global__ void k_bnapply(float* __restrict__ out) {
    int t = blockIdx.x * blockDim.x + threadIdx.x;
    if (t >= NN * 16) return;
    int h4 = t & 15;
    float4 v  = ((float4*)out)[t];
    float4 sc = ((const float4*)g_bnscale)[h4];
    float4 sh = ((const float4*)g_bnshift)[h4];
    v.x = v.x * sc.x + sh.x; v.x = v.x > 0.f ? v.x : 0.01f * v.x;
    v.y = v.y * sc.y + sh.y; v.y = v.y > 0.f ? v.y : 0.01f * v.y;
    v.z = v.z * sc.z + sh.z; v.z = v.z > 0.f ? v.z : 0.01f * v.z;
    v.w = v.w * sc.w + sh.w; v.w = v.w > 0.f ? v.w : 0.01f * v.w;
    ((float4*)out)[t] = v;
}

// ---------------- launch ----------------
extern "C" void kernel_launch(void* const* d_in, const int* in_sizes, int n_in,
                              void* d_out, int out_size) {
    const float* x     = (const float*)d_in[0];
    const int*   ei    = (const int*)d_in[1];
    const int*   et    = (const int*)d_in[2];
    const float* W1    = (const float*)d_in[3];
    const float* q1    = (const float*)d_in[4];
    const float* k1    = (const float*)d_in[5];
    const float* b1    = (const float*)d_in[6];
    const float* W2    = (const float*)d_in[7];
    const float* q2    = (const float*)d_in[8];
    const float* k2    = (const float*)d_in[9];
    const float* b2    = (const float*)d_in[10];
    const float* gamma = (const float*)d_in[11];
    const float* beta  = (const float*)d_in[12];
    float* out = (float*)d_out;

    const int TPB = 256;
    dim3 gemmGrid(4, (NN + 127) / 128);

    k_zero<<<(NN + TPB - 1) / TPB, TPB>>>();                       // 0
    k_cvtA<<<(NN * 32 + TPB - 1) / TPB, TPB>>>(x);                 // 1
    k_wt<<<(GG * CC + TPB - 1) / TPB, TPB>>>(W1, GG);              // 2
    k_gemm<<<gemmGrid, TPB>>>(NN, GG, 0, q1, k1);                  // 3 <- profiled
    k_decode<<<(EE + TPB - 1) / TPB, TPB>>>(ei, et);               // 4
    k_scan1<<<NBLK, SCAN_B>>>();                                   // 5
    k_scan2<<<1, 256>>>();                                         // 6
    k_scan3<<<(NN + TPB - 1) / TPB, TPB>>>();                      // 7
    k_scatter<<<(EE + TPB - 1) / TPB, TPB>>>();                    // 8
    k_agg<<<(NN * 32 + TPB - 1) / TPB, TPB>>>(b1, nullptr, 1);     // 9

    // ---- layer 2 ----
    k_wt<<<(HH * CC + TPB - 1) / TPB, TPB>>>(W2, HH);
    k_gemm<<<gemmGrid, TPB>>>(NN, HH, 1, q2, k2);
    k_agg<<<(NN * 32 + TPB - 1) / TPB, TPB>>>(b2, out, 0);

    // ---- batchnorm + leaky ----
    k_bnstats<<<(1024 * 32) / TPB, TPB>>>(out);
    k_bnfinal<<<1, HH>>>(gamma, beta);
    k_bnapply<<<(NN * 16 + TPB - 1) / TPB, TPB>>>(out);
}

// round 13
// speedup vs baseline: 1.2101x; 1.0139x over previous
#include <cuda_runtime.h>
#include <cuda_fp16.h>
#include <math.h>
#include <stdint.h>

#define NN 100000
#define EE 1600000
#define RR 8
#define GG 128
#define HH 64
#define CC 512   // RR*HH
#define SCAN_B 512
#define NBLK ((NN + SCAN_B - 1) / SCAN_B)   // 196

// ---------------- scratch ----------------
__device__ __half g_xw[(size_t)RR * NN * HH];  // [r][n][h] fp16
__device__ __half g_xa[(size_t)NN * GG];       // fp16 input features
__device__ __half g_WT[GG * CC];               // [r*64+o][k] fp16 (n-major)
__device__ float g_sq[RR * NN];
__device__ float g_sk[RR * NN];
__device__ int   g_rs[EE];
__device__ int   g_dstl[EE];
__device__ int   g_sorted[EE];
__device__ int   g_cnt[NN];
__device__ int   g_wpos[NN];
__device__ int   g_off[NN];
__device__ int   g_scan[NN];
__device__ int   g_bsum[256];
__device__ int   g_bpre[256];
__device__ __half g_x1[NN * HH];               // fp16 layer-1 output
__device__ float g_bnsum[HH];
__device__ float g_bnsqs[HH];
__device__ float g_bnscale[HH];
__device__ float g_bnshift[HH];

// ---------------- sort-by-dst pipeline ----------------
__global__ void k_zero() {
    int i = blockIdx.x * blockDim.x + threadIdx.x;
    if (i < NN) { g_cnt[i] = 0; g_wpos[i] = 0; }
    if (i < HH) { g_bnsum[i] = 0.f; g_bnsqs[i] = 0.f; }
}

__global__ void k_decode(const int* __restrict__ ei, const int* __restrict__ et) {
    int e = blockIdx.x * blockDim.x + threadIdx.x;
    if (e >= EE) return;
    int s = min(max(ei[e], 0), NN - 1);
    int d = min(max(ei[EE + e], 0), NN - 1);
    int r = min(max(et[e], 0), RR - 1);
    g_rs[e]   = r * NN + s;
    g_dstl[e] = d;
    atomicAdd(&g_cnt[d], 1);
}

__global__ void k_scan1() {
    __shared__ int s[SCAN_B];
    int tid = threadIdx.x;
    int i = blockIdx.x * SCAN_B + tid;
    int v = (i < NN) ? g_cnt[i] : 0;
    s[tid] = v;
    __syncthreads();
    for (int d = 1; d < SCAN_B; d <<= 1) {
        int t = (tid >= d) ? s[tid - d] : 0;
        __syncthreads();
        s[tid] += t;
        __syncthreads();
    }
    if (i < NN) g_scan[i] = s[tid];
    if (tid == SCAN_B - 1) g_bsum[blockIdx.x] = s[tid];
}

__global__ void k_scan2() {
    __shared__ int s[256];
    int tid = threadIdx.x;
    int v = (tid < NBLK) ? g_bsum[tid] : 0;
    s[tid] = v;
    __syncthreads();
    for (int d = 1; d < 256; d <<= 1) {
        int t = (tid >= d) ? s[tid - d] : 0;
        __syncthreads();
        s[tid] += t;
        __syncthreads();
    }
    if (tid < NBLK) g_bpre[tid] = s[tid] - v;
}

__global__ void k_scan3() {
    int i = blockIdx.x * blockDim.x + threadIdx.x;
    if (i >= NN) return;
    g_off[i] = g_scan[i] - g_cnt[i] + g_bpre[i >> 9];
}

__global__ void k_scatter() {
    int e = blockIdx.x * blockDim.x + threadIdx.x;
    if (e >= EE) return;
    int d = g_dstl[e];
    int pos = g_off[d] + atomicAdd(&g_wpos[d], 1);
    g_sorted[pos] = g_rs[e];
}

// W [R,K,H] -> WT [r*64+o][k] fp16
__global__ void k_wt(const float* __restrict__ W, int K) {
    int idx = blockIdx.x * blockDim.x + threadIdx.x;
    if (idx >= K * CC) return;
    int c = idx / K, i = idx % K;
    int r = c >> 6, o = c & 63;
    g_WT[idx] = __float2half_rn(W[((size_t)r * K + i) * HH + o]);
}

// x -> g_xa fp16
__global__ void k_cvtA(const float* __restrict__ x) {
    int i = blockIdx.x * blockDim.x + threadIdx.x;
    if (i >= NN * (GG / 4)) return;
    float4 v = ((const float4*)x)[i];
    __half2 h0 = __floats2half2_rn(v.x, v.y);
    __half2 h1 = __floats2half2_rn(v.z, v.w);
    ((uint2*)g_xa)[i] = make_uint2(*(uint32_t*)&h0, *(uint32_t*)&h1);
}

// ---------------- fp16 tensor-core GEMM + fused scores (pipelined) ----------------
#define PADH 40

__device__ __forceinline__ void cpa16(uint32_t smem_addr, const void* gptr, int sz) {
    asm volatile("cp.async.ca.shared.global [%0], [%1], 16, %2;\n"
                 :: "r"(smem_addr), "l"(gptr), "r"(sz));
}

__global__ void __launch_bounds__(256)
k_gemm(int M, int K, int useX1,
       const float* __restrict__ qv_g, const float* __restrict__ kv_g) {
    const __half* __restrict__ A = useX1 ? g_x1 : g_xa;
    __shared__ __half Ah[2][128 * PADH];
    __shared__ __half Bh[2][128 * PADH];
    __shared__ float qs[64], ks[64];

    int rp = blockIdx.x;
    int rowBase = blockIdx.y * 128;
    int tid = threadIdx.x;
    int warp = tid >> 5, lane = tid & 31;
    int wr = warp >> 1, wc = warp & 1;
    int g = lane >> 2, t = lane & 3;

    uint32_t AhS0 = (uint32_t)__cvta_generic_to_shared(Ah[0]);
    uint32_t AhS1 = (uint32_t)__cvta_generic_to_shared(Ah[1]);
    uint32_t BhS0 = (uint32_t)__cvta_generic_to_shared(Bh[0]);
    uint32_t BhS1 = (uint32_t)__cvta_generic_to_shared(Bh[1]);

    if (tid < 64)        qs[tid] = qv_g[tid];
    else if (tid < 128)  ks[tid - 64] = kv_g[tid - 64];

    float acc[2][8][4];
    #pragma unroll
    for (int i = 0; i < 2; i++)
        #pragma unroll
        for (int j = 0; j < 8; j++)
            #pragma unroll
            for (int l = 0; l < 4; l++) acc[i][j][l] = 0.f;

    int nChunks = K >> 5;
    int lrow = tid >> 1;
    int lc8  = (tid & 1) * 8;
    int lm_row = (lane & 7) + ((lane >> 3) & 1) * 8;
    int lm_c8  = (lane >> 4) * 8;
    int grow_l = rowBase + lrow;
    bool okA = (grow_l < M);
    const __half* aSrc = A + (size_t)grow_l * K;
    const __half* bSrc = g_WT + (size_t)(rp * 128 + lrow) * K;

    // prefetch chunk 0 into buf 0
    #pragma unroll
    for (int p = 0; p < 2; p++) {
        int c8 = lc8 + p * 16;
        cpa16(AhS0 + (lrow * PADH + c8) * 2, aSrc + c8, okA ? 16 : 0);
        cpa16(BhS0 + (lrow * PADH + c8) * 2, bSrc + c8, 16);
    }
    asm volatile("cp.async.commit_group;\n");

    for (int c = 0; c < nChunks; c++) {
        int cur = c & 1;
        if (c + 1 < nChunks) {
            int kb = (c + 1) << 5;
            uint32_t AhN = cur ? AhS0 : AhS1;
            uint32_t BhN = cur ? BhS0 : BhS1;
            #pragma unroll
            for (int p = 0; p < 2; p++) {
                int c8 = lc8 + p * 16;
                cpa16(AhN + (lrow * PADH + c8) * 2, aSrc + kb + c8, okA ? 16 : 0);
                cpa16(BhN + (lrow * PADH + c8) * 2, bSrc + kb + c8, 16);
            }
            asm volatile("cp.async.commit_group;\n");
            asm volatile("cp.async.wait_group 1;\n");
        } else {
            asm volatile("cp.async.wait_group 0;\n");
        }
        __syncthreads();

        uint32_t AhC = cur ? AhS1 : AhS0;
        const uint32_t* BsuC = (const uint32_t*)(cur ? Bh[1] : Bh[0]);

        #pragma unroll
        for (int ks16 = 0; ks16 < 2; ks16++) {
            uint32_t af[2][4];
            #pragma unroll
            for (int mt = 0; mt < 2; mt++) {
                int row = wr * 32 + mt * 16 + lm_row;
                uint32_t addr = AhC + (row * PADH + ks16 * 16 + lm_c8) * 2;
                asm volatile(
                    "ldmatrix.sync.aligned.m8n8.x4.shared.b16 {%0,%1,%2,%3}, [%4];\n"
                    : "=r"(af[mt][0]), "=r"(af[mt][1]), "=r"(af[mt][2]), "=r"(af[mt][3])
                    : "r"(addr));
            }
            #pragma unroll
            for (int nt = 0; nt < 8; nt++) {
                int n = wc * 64 + nt * 8 + g;
                uint32_t b0 = BsuC[n * (PADH / 2) + ks16 * 8 + t];
                uint32_t b1 = BsuC[n * (PADH / 2) + ks16 * 8 + t + 4];
                #pragma unroll
                for (int mt = 0; mt < 2; mt++) {
                    asm volatile(
                        "mma.sync.aligned.m16n8k16.row.col.f32.f16.f16.f32 "
                        "{%0,%1,%2,%3}, {%4,%5,%6,%7}, {%8,%9}, {%0,%1,%2,%3};\n"
                        : "+f"(acc[mt][nt][0]), "+f"(acc[mt][nt][1]),
                          "+f"(acc[mt][nt][2]), "+f"(acc[mt][nt][3])
                        : "r"(af[mt][0]), "r"(af[mt][1]), "r"(af[mt][2]), "r"(af[mt][3]),
                          "r"(b0), "r"(b1));
                }
            }
        }
        __syncthreads();
    }

    int rel = 2 * rp + wc;
    float qv[16], kv[16];
    #pragma unroll
    for (int nt = 0; nt < 8; nt++) {
        int o0 = nt * 8 + 2 * t;
        qv[2 * nt] = qs[o0]; qv[2 * nt + 1] = qs[o0 + 1];
        kv[2 * nt] = ks[o0]; kv[2 * nt + 1] = ks[o0 + 1];
    }
    __half2* xwh = (__half2*)g_xw;
    #pragma unroll
    for (int mt = 0; mt < 2; mt++) {
        #pragma unroll
        for (int h = 0; h < 2; h++) {
            int row_l = wr * 32 + mt * 16 + g + h * 8;
            int grow = rowBase + row_l;
            bool ok = (grow < M);
            float pq = 0.f, pk = 0.f;
            #pragma unroll
            for (int nt = 0; nt < 8; nt++) {
                float c0 = acc[mt][nt][h * 2 + 0];
                float c1 = acc[mt][nt][h * 2 + 1];
                if (ok) {
                    xwh[((size_t)rel * NN + grow) * 32 + nt * 4 + t] =
                        __floats2half2_rn(c0, c1);
                }
                pq += c0 * qv[2 * nt] + c1 * qv[2 * nt + 1];
                pk += c0 * kv[2 * nt] + c1 * kv[2 * nt + 1];
            }
            pq += __shfl_xor_sync(0xffffffffu, pq, 1);
            pq += __shfl_xor_sync(0xffffffffu, pq, 2);
            pk += __shfl_xor_sync(0xffffffffu, pk, 1);
            pk += __shfl_xor_sync(0xffffffffu, pk, 2);
            if (ok && t == 0) {
                g_sq[rel * NN + grow] = pq;
                g_sk[rel * NN + grow] = pk;
            }
        }
    }
}

// ---------------- segmented softmax-aggregate: one warp per node ----------------
__global__ void k_agg(const float* __restrict__ b, float* outParam, int mode) {
    int gw = (blockIdx.x * blockDim.x + threadIdx.x) >> 5;
    int lane = threadIdx.x & 31;
    if (gw >= NN) return;
    int node = gw;
    int beg = g_off[node];
    int cnt = g_cnt[node];
    const __half2* xwh = (const __half2*)g_xw;

    float2 acc = make_float2(0.f, 0.f);
    float denom = 0.f;

    if (cnt <= 32) {
        int rs_l = 0;
        float a_l = -INFINITY;
        if (lane < cnt) {
            rs_l = g_sorted[beg + lane];
            int r = rs_l / NN;
            float a = g_sq[r * NN + node] + g_sk[rs_l];
            a_l = a > 0.f ? a : 0.2f * a;
        }
        float m = a_l;
        #pragma unroll
        for (int off = 16; off; off >>= 1)
            m = fmaxf(m, __shfl_xor_sync(0xffffffffu, m, off));
        float w_l = (lane < cnt) ? __expf(a_l - m) : 0.f;
        float ds = w_l;
        #pragma unroll
        for (int off = 16; off; off >>= 1)
            ds += __shfl_xor_sync(0xffffffffu, ds, off);
        denom = ds;
        int i = 0;
        for (; i + 2 <= cnt; i += 2) {
            int rs0 = __shfl_sync(0xffffffffu, rs_l, i);
            int rs1 = __shfl_sync(0xffffffffu, rs_l, i + 1);
            float w0 = __shfl_sync(0xffffffffu, w_l, i);
            float w1 = __shfl_sync(0xffffffffu, w_l, i + 1);
            float2 v0 = __half22float2(xwh[(size_t)rs0 * 32 + lane]);
            float2 v1 = __half22float2(xwh[(size_t)rs1 * 32 + lane]);
            acc.x += w0 * v0.x + w1 * v1.x;
            acc.y += w0 * v0.y + w1 * v1.y;
        }
        if (i < cnt) {
            int rs0 = __shfl_sync(0xffffffffu, rs_l, i);
            float w0 = __shfl_sync(0xffffffffu, w_l, i);
            float2 v0 = __half22float2(xwh[(size_t)rs0 * 32 + lane]);
            acc.x += w0 * v0.x;
            acc.y += w0 * v0.y;
        }
    } else {
        float m = -INFINITY;
        for (int i = lane; i < cnt; i += 32) {
            int rs = g_sorted[beg + i];
            int r = rs / NN;
            float a = g_sq[r * NN + node] + g_sk[rs];
            a = a > 0.f ? a : 0.2f * a;
            m = fmaxf(m, a);
        }
        #pragma unroll
        for (int off = 16; off; off >>= 1)
            m = fmaxf(m, __shfl_xor_sync(0xffffffffu, m, off));
        for (int i = 0; i < cnt; i++) {
            int rs = g_sorted[beg + i];
            int r = rs / NN;
            float a = g_sq[r * NN + node] + g_sk[rs];
            a = a > 0.f ? a : 0.2f * a;
            float w = __expf(a - m);
            denom += w;
            float2 v = __half22float2(xwh[(size_t)rs * 32 + lane]);
            acc.x += w * v.x;
            acc.y += w * v.y;
        }
    }

    float inv = 1.f / (denom + 1e-16f);
    float2 bb = ((const float2*)b)[lane];
    float ox = acc.x * inv + bb.x;
    float oy = acc.y * inv + bb.y;
    if (mode == 1) {
        ox = fmaxf(ox, 0.f);
        oy = fmaxf(oy, 0.f);
        ((__half2*)g_x1)[(size_t)node * 32 + lane] = __floats2half2_rn(ox, oy);
    } else {
        ((float2*)outParam)[(size_t)node * 32 + lane] = make_float2(ox, oy);
    }
}

// ---------------- batchnorm ----------------
__global__ void k_bnstats(const float* __restrict__ out) {
    int gw = (blockIdx.x * blockDim.x + threadIdx.x) >> 5;
    int lane = threadIdx.x & 31;
    const int CHUNK = 98;
    int n0 = gw * CHUNK;
    float2 s = make_float2(0.f, 0.f), s2 = make_float2(0.f, 0.f);
    for (int n = n0; n < n0 + CHUNK && n < NN; n++) {
        float2 v = ((const float2*)out)[(size_t)n * 32 + lane];
        s.x += v.x; s.y += v.y;
        s2.x += v.x * v.x; s2.y += v.y * v.y;
    }
    atomicAdd(&g_bnsum[2 * lane], s.x);     atomicAdd(&g_bnsum[2 * lane + 1], s.y);
    atomicAdd(&g_bnsqs[2 * lane], s2.x);    atomicAdd(&g_bnsqs[2 * lane + 1], s2.y);
}

__global__ void k_bnfinal(const float* __restrict__ gamma, const float* __restrict__ beta) {
    int h = threadIdx.x;
    if (h < HH) {
        float mean = g_bnsum[h] * (1.f / NN);
        float var  = g_bnsqs[h] * (1.f / NN) - mean * mean;
        float sc = gamma[h] * rsqrtf(var + 1e-5f);
        g_bnscale[h] = sc;
        g_bnshift[h] = beta[h] - mean * sc;
    }
}

__global__ void k_bnapply(float* __restrict__ out) {
    int t = blockIdx.x * blockDim.x + threadIdx.x;
    if (t >= NN * 16) return;
    int h4 = t & 15;
    float4 v  = ((float4*)out)[t];
    float4 sc = ((const float4*)g_bnscale)[h4];
    float4 sh = ((const float4*)g_bnshift)[h4];
    v.x = v.x * sc.x + sh.x; v.x = v.x > 0.f ? v.x : 0.01f * v.x;
    v.y = v.y * sc.y + sh.y; v.y = v.y > 0.f ? v.y : 0.01f * v.y;
    v.z = v.z * sc.z + sh.z; v.z = v.z > 0.f ? v.z : 0.01f * v.z;
    v.w = v.w * sc.w + sh.w; v.w = v.w > 0.f ? v.w : 0.01f * v.w;
    ((float4*)out)[t] = v;
}

// ---------------- launch ----------------
extern "C" void kernel_launch(void* const* d_in, const int* in_sizes, int n_in,
                              void* d_out, int out_size) {
    const float* x     = (const float*)d_in[0];
    const int*   ei    = (const int*)d_in[1];
    const int*   et    = (const int*)d_in[2];
    const float* W1    = (const float*)d_in[3];
    const float* q1    = (const float*)d_in[4];
    const float* k1    = (const float*)d_in[5];
    const float* b1    = (const float*)d_in[6];
    const float* W2    = (const float*)d_in[7];
    const float* q2    = (const float*)d_in[8];
    const float* k2    = (const float*)d_in[9];
    const float* b2    = (const float*)d_in[10];
    const float* gamma = (const float*)d_in[11];
    const float* beta  = (const float*)d_in[12];
    float* out = (float*)d_out;

    const int TPB = 256;
    dim3 gemmGrid(4, (NN + 127) / 128);

    k_zero<<<(NN + TPB - 1) / TPB, TPB>>>();                       // 0
    k_cvtA<<<(NN * 32 + TPB - 1) / TPB, TPB>>>(x);                 // 1
    k_wt<<<(GG * CC + TPB - 1) / TPB, TPB>>>(W1, GG);              // 2
    k_gemm<<<gemmGrid, TPB>>>(NN, GG, 0, q1, k1);                  // 3 <- profiled
    k_decode<<<(EE + TPB - 1) / TPB, TPB>>>(ei, et);               // 4
    k_scan1<<<NBLK, SCAN_B>>>();                                   // 5
    k_scan2<<<1, 256>>>();                                         // 6
    k_scan3<<<(NN + TPB - 1) / TPB, TPB>>>();                      // 7
    k_scatter<<<(EE + TPB - 1) / TPB, TPB>>>();                    // 8
    k_agg<<<(NN * 32 + TPB - 1) / TPB, TPB>>>(b1, nullptr, 1);     // 9

    // ---- layer 2 ----
    k_wt<<<(HH * CC + TPB - 1) / TPB, TPB>>>(W2, HH);
    k_gemm<<<gemmGrid, TPB>>>(NN, HH, 1, q2, k2);
    k_agg<<<(NN * 32 + TPB - 1) / TPB, TPB>>>(b2, out, 0);

    // ---- batchnorm + leaky ----
    k_bnstats<<<(1024 * 32) / TPB, TPB>>>(out);
    k_bnfinal<<<1, HH>>>(gamma, beta);
    k_bnapply<<<(NN * 16 + TPB - 1) / TPB, TPB>>>(out);
}